// round 10
// baseline (speedup 1.0000x reference)
#include <cuda_runtime.h>

// ChamferIndex recipe-probe round.
// out0: DOT = DESCENDING fma chain, epilogue A   (probe cublas k-loop direction)
// out1: DOT = ascending fma chain,  epilogue D   (probe fusion association)
// Common: norms = mul + L2R add (no fma), first-min strict '<' tie-break.

#define THREADS 128
#define XPT     2
#define XPB     (THREADS * XPT)     // 256 x points per block
#define TILE    2048                // 32 KB smem as float4
#define BATCH   8
#define NPTS    16384
#define HALF    (BATCH * NPTS)

__device__ __forceinline__ float norm3_nofma(float a, float b, float c) {
    return __fadd_rn(__fadd_rn(__fmul_rn(a, a), __fmul_rn(b, b)),
                     __fmul_rn(c, c));
}

// DOT_MODE: 1 = ascending fma (x0 first), 2 = descending fma (x2 first)
// EPI_MODE: 0 = rn(rn(xx+yn) - 2dot)   1 = rn(xx + rn(yn - 2dot))
template<int DOT_MODE, int EPI_MODE>
__global__ void nn_kernel(const float* __restrict__ X,
                          const float* __restrict__ Y,
                          float* __restrict__ O)
{
    const int blk = blockIdx.x;
    const int b   = blk / (NPTS / XPB);
    const int cx  = blk % (NPTS / XPB);
    const int tid = threadIdx.x;

    __shared__ float4 sy[TILE];

    float xa[XPT], xb[XPT], xc[XPT], xx[XPT], best[XPT];
    int   bidx[XPT], xi[XPT];

#pragma unroll
    for (int k = 0; k < XPT; k++) {
        int i = cx * XPB + k * THREADS + tid;
        xi[k] = i;
        const float* xp = X + ((long)b * NPTS + i) * 3;
        float a = xp[0], bb = xp[1], c = xp[2];
        xa[k] = a; xb[k] = bb; xc[k] = c;
        xx[k] = norm3_nofma(a, bb, c);
        best[k] = 3.4e38f;
        bidx[k] = 0;
    }

    const float* __restrict__ Yb = Y + (long)b * NPTS * 3;

    for (int t0 = 0; t0 < NPTS; t0 += TILE) {
        __syncthreads();
        for (int j = tid; j < TILE; j += THREADS) {
            const float* yp = Yb + (long)(t0 + j) * 3;
            float y0 = yp[0], y1 = yp[1], y2 = yp[2];
            sy[j] = make_float4(y0, y1, y2, norm3_nofma(y0, y1, y2));
        }
        __syncthreads();

#pragma unroll 8
        for (int j = 0; j < TILE; j++) {
            float4 y = sy[j];
#pragma unroll
            for (int k = 0; k < XPT; k++) {
                float dot;
                if (DOT_MODE == 1) {            // ascending fma
                    dot = __fmul_rn(xa[k], y.x);
                    dot = __fmaf_rn(xb[k], y.y, dot);
                    dot = __fmaf_rn(xc[k], y.z, dot);
                } else {                        // descending fma
                    dot = __fmul_rn(xc[k], y.z);
                    dot = __fmaf_rn(xb[k], y.y, dot);
                    dot = __fmaf_rn(xa[k], y.x, dot);
                }
                float t2 = __fadd_rn(dot, dot);   // 2*dot, exact
                float d;
                if (EPI_MODE == 0) {
                    d = __fsub_rn(__fadd_rn(xx[k], y.w), t2);
                } else {
                    d = __fadd_rn(xx[k], __fsub_rn(y.w, t2));
                }
                if (d < best[k]) { best[k] = d; bidx[k] = t0 + j; }
            }
        }
    }

#pragma unroll
    for (int k = 0; k < XPT; k++)
        O[(long)b * NPTS + xi[k]] = (float)bidx[k];
}

extern "C" void kernel_launch(void* const* d_in, const int* in_sizes, int n_in,
                              void* d_out, int out_size) {
    const float* x1 = (const float*)d_in[0];
    const float* x2 = (const float*)d_in[1];
    float* out = (float*)d_out;

    const int blocks = (NPTS / XPB) * BATCH;   // 512 per direction

    nn_kernel<2, 0><<<blocks, THREADS>>>(x1, x2, out);          // out0: desc dot, epi A
    nn_kernel<1, 1><<<blocks, THREADS>>>(x2, x1, out + HALF);   // out1: asc dot,  epi D
}

// round 11
// speedup vs baseline: 1.1825x; 1.1825x over previous
#include <cuda_runtime.h>

// ChamferIndex: bidirectional NN argmin, indices as FLOAT values.
// xyz1, xyz2: [8, 16384, 3] fp32. out (float32): [idx1(131072), idx2(131072)].
//
// Exact XLA recipe (validated in round 10, out1 == 0.0):
//   norms: mul + left-to-right add (no fma)
//   dot:   ascending fma chain  rn(fma(x2,y2, fma(x1,y1, rn(x0*y0))))
//   d:     rn(xx + rn(yn - 2*dot))        (2*dot exact)
//   argmin: first-min, strict '<'
//
// Perf: packed f32x2 math (2 x-points per instruction, per-lane rn identical
// to scalar), y staged in smem pre-duplicated for direct LDS.128 packed
// operands, both directions fused in one launch (1024 blocks).

#define THREADS 128
#define XPT     2                   // x points per thread (one f32x2 group)
#define XPB     (THREADS * XPT)     // 256 x points per block
#define TILE    1024                // y points per smem tile (32 KB duplicated)
#define BATCH   8
#define NPTS    16384
#define HALF    (BATCH * NPTS)

typedef unsigned long long u64;

__device__ __forceinline__ u64 pack2(float lo, float hi) {
    u64 r; asm("mov.b64 %0, {%1, %2};" : "=l"(r) : "f"(lo), "f"(hi)); return r;
}
__device__ __forceinline__ void unpack2(float& lo, float& hi, u64 v) {
    asm("mov.b64 {%0, %1}, %2;" : "=f"(lo), "=f"(hi) : "l"(v));
}
__device__ __forceinline__ u64 mul2(u64 a, u64 b) {
    u64 r; asm("mul.rn.f32x2 %0, %1, %2;" : "=l"(r) : "l"(a), "l"(b)); return r;
}
__device__ __forceinline__ u64 fma2(u64 a, u64 b, u64 c) {
    u64 r; asm("fma.rn.f32x2 %0, %1, %2, %3;" : "=l"(r) : "l"(a), "l"(b), "l"(c)); return r;
}
__device__ __forceinline__ u64 add2(u64 a, u64 b) {
    u64 r; asm("add.rn.f32x2 %0, %1, %2;" : "=l"(r) : "l"(a), "l"(b)); return r;
}
__device__ __forceinline__ u64 sub2(u64 a, u64 b) {
    u64 r; asm("sub.rn.f32x2 %0, %1, %2;" : "=l"(r) : "l"(a), "l"(b)); return r;
}

__device__ __forceinline__ float norm3_nofma(float a, float b, float c) {
    return __fadd_rn(__fadd_rn(__fmul_rn(a, a), __fmul_rn(b, b)),
                     __fmul_rn(c, c));
}

__global__ void nn_kernel(const float* __restrict__ x1,
                          const float* __restrict__ x2,
                          float* __restrict__ out)
{
    const int dir = blockIdx.z;
    const float* __restrict__ X = dir ? x2 : x1;
    const float* __restrict__ Y = dir ? x1 : x2;
    float* __restrict__ O = out + dir * HALF;

    const int b   = blockIdx.y;
    const int cx  = blockIdx.x;
    const int tid = threadIdx.x;

    // Duplicated y layout: syA[j] = {y0,y0 | y1,y1}, syB[j] = {y2,y2 | yn,yn}
    __shared__ ulonglong2 syA[TILE];
    __shared__ ulonglong2 syB[TILE];

    // Two x-points per thread, packed into f32x2 operands.
    int i0 = cx * XPB + tid;             // point 0
    int i1 = i0 + THREADS;               // point 1
    const float* xp0 = X + ((long)b * NPTS + i0) * 3;
    const float* xp1 = X + ((long)b * NPTS + i1) * 3;
    float a0 = xp0[0], b0 = xp0[1], c0 = xp0[2];
    float a1 = xp1[0], b1 = xp1[1], c1 = xp1[2];

    u64 xa2 = pack2(a0, a1);
    u64 xb2 = pack2(b0, b1);
    u64 xc2 = pack2(c0, c1);
    u64 xx2 = pack2(norm3_nofma(a0, b0, c0), norm3_nofma(a1, b1, c1));

    float best0 = 3.4e38f, best1 = 3.4e38f;
    int   idx0 = 0, idx1 = 0;

    const float* __restrict__ Yb = Y + (long)b * NPTS * 3;

    for (int t0 = 0; t0 < NPTS; t0 += TILE) {
        __syncthreads();
        for (int j = tid; j < TILE; j += THREADS) {
            const float* yp = Yb + (long)(t0 + j) * 3;
            float y0 = yp[0], y1 = yp[1], y2 = yp[2];
            float yn = norm3_nofma(y0, y1, y2);
            syA[j] = make_ulonglong2(pack2(y0, y0), pack2(y1, y1));
            syB[j] = make_ulonglong2(pack2(y2, y2), pack2(yn, yn));
        }
        __syncthreads();

#pragma unroll 4
        for (int j = 0; j < TILE; j++) {
            ulonglong2 A = syA[j];   // LDS.128 broadcast: {y0,y0},{y1,y1}
            ulonglong2 B = syB[j];   // {y2,y2},{yn,yn}

            u64 dot = mul2(xa2, A.x);        // ascending fma chain (per-lane rn)
            dot = fma2(xb2, A.y, dot);
            dot = fma2(xc2, B.x, dot);
            u64 t  = add2(dot, dot);         // 2*dot (exact)
            u64 u  = sub2(B.y, t);           // yn - 2*dot
            u64 d2 = add2(xx2, u);           // xx + (yn - 2*dot)   (epilogue D)

            float d0, d1;
            unpack2(d0, d1, d2);
            int jj = t0 + j;
            idx0  = (d0 < best0) ? jj : idx0;     // strict '<': first-min
            best0 = fminf(best0, d0);
            idx1  = (d1 < best1) ? jj : idx1;
            best1 = fminf(best1, d1);
        }
    }

    O[(long)b * NPTS + i0] = (float)idx0;
    O[(long)b * NPTS + i1] = (float)idx1;
}

extern "C" void kernel_launch(void* const* d_in, const int* in_sizes, int n_in,
                              void* d_out, int out_size) {
    const float* x1 = (const float*)d_in[0];
    const float* x2 = (const float*)d_in[1];
    float* out = (float*)d_out;

    dim3 grid(NPTS / XPB, BATCH, 2);   // 64 x-chunks, 8 batches, 2 directions
    nn_kernel<<<grid, THREADS>>>(x1, x2, out);
}

// round 12
// speedup vs baseline: 1.5884x; 1.3433x over previous
#include <cuda_runtime.h>

// ChamferIndex: bidirectional NN argmin, indices as FLOAT values.
// xyz1, xyz2: [8, 16384, 3] fp32. out (float32): [idx1(131072), idx2(131072)].
//
// Validated XLA value recipe (round 10): norms = mul + L2R add (no fma);
// dot = ascending fma chain; d = rn(xx + rn(yn - 2*dot)); first-min '<'.
//
// Perf: f32x2 packed math (2 x-points/instr), smem y pre-duplicated for
// direct LDS.128 packed operands, fused directions, and DEFERRED ARGMIN:
// inner loop keeps only a 16-wide group min (2 FMNMX/j, no index ops);
// on the rare group improvement, rescan the 16 j's with the identical
// instruction sequence (bit-exact) and take the first d == best.

#define THREADS 128
#define XPB     256                 // x points per block (2 per thread)
#define TILE    1024                // y points per smem tile
#define GRP     16                  // deferred-argmin group size
#define BATCH   8
#define NPTS    16384
#define HALF    (BATCH * NPTS)

typedef unsigned long long u64;

__device__ __forceinline__ u64 pack2(float lo, float hi) {
    u64 r; asm("mov.b64 %0, {%1, %2};" : "=l"(r) : "f"(lo), "f"(hi)); return r;
}
__device__ __forceinline__ void unpack2(float& lo, float& hi, u64 v) {
    asm("mov.b64 {%0, %1}, %2;" : "=f"(lo), "=f"(hi) : "l"(v));
}
__device__ __forceinline__ u64 mul2(u64 a, u64 b) {
    u64 r; asm("mul.rn.f32x2 %0, %1, %2;" : "=l"(r) : "l"(a), "l"(b)); return r;
}
__device__ __forceinline__ u64 fma2(u64 a, u64 b, u64 c) {
    u64 r; asm("fma.rn.f32x2 %0, %1, %2, %3;" : "=l"(r) : "l"(a), "l"(b), "l"(c)); return r;
}
__device__ __forceinline__ u64 add2(u64 a, u64 b) {
    u64 r; asm("add.rn.f32x2 %0, %1, %2;" : "=l"(r) : "l"(a), "l"(b)); return r;
}
__device__ __forceinline__ u64 sub2(u64 a, u64 b) {
    u64 r; asm("sub.rn.f32x2 %0, %1, %2;" : "=l"(r) : "l"(a), "l"(b)); return r;
}

__device__ __forceinline__ float norm3_nofma(float a, float b, float c) {
    return __fadd_rn(__fadd_rn(__fmul_rn(a, a), __fmul_rn(b, b)),
                     __fmul_rn(c, c));
}

// d for both packed x-points against y-entry (A,B). Identical sequence is
// used in the main loop and in rescans -> bit-identical results.
__device__ __forceinline__ u64 dist2(u64 xa2, u64 xb2, u64 xc2, u64 xx2,
                                     ulonglong2 A, ulonglong2 B) {
    u64 dot = mul2(xa2, A.x);          // ascending fma chain
    dot = fma2(xb2, A.y, dot);
    dot = fma2(xc2, B.x, dot);
    u64 t = add2(dot, dot);            // 2*dot (exact)
    return add2(xx2, sub2(B.y, t));    // xx + (yn - 2*dot)
}

__global__ void nn_kernel(const float* __restrict__ x1,
                          const float* __restrict__ x2,
                          float* __restrict__ out)
{
    const int dir = blockIdx.z;
    const float* __restrict__ X = dir ? x2 : x1;
    const float* __restrict__ Y = dir ? x1 : x2;
    float* __restrict__ O = out + dir * HALF;

    const int b   = blockIdx.y;
    const int cx  = blockIdx.x;
    const int tid = threadIdx.x;

    __shared__ ulonglong2 syA[TILE];   // {y0,y0 | y1,y1}
    __shared__ ulonglong2 syB[TILE];   // {y2,y2 | yn,yn}

    const int i0 = cx * XPB + tid;
    const int i1 = i0 + THREADS;
    const float* xp0 = X + ((long)b * NPTS + i0) * 3;
    const float* xp1 = X + ((long)b * NPTS + i1) * 3;
    float a0 = xp0[0], b0 = xp0[1], c0 = xp0[2];
    float a1 = xp1[0], b1 = xp1[1], c1 = xp1[2];

    const u64 xa2 = pack2(a0, a1);
    const u64 xb2 = pack2(b0, b1);
    const u64 xc2 = pack2(c0, c1);
    const u64 xx2 = pack2(norm3_nofma(a0, b0, c0), norm3_nofma(a1, b1, c1));

    float best0 = 3.4e38f, best1 = 3.4e38f;
    int   idx0 = 0, idx1 = 0;

    const float* __restrict__ Yb = Y + (long)b * NPTS * 3;

    for (int t0 = 0; t0 < NPTS; t0 += TILE) {
        __syncthreads();
        for (int j = tid; j < TILE; j += THREADS) {
            const float* yp = Yb + (long)(t0 + j) * 3;
            float y0 = yp[0], y1 = yp[1], y2 = yp[2];
            float yn = norm3_nofma(y0, y1, y2);
            syA[j] = make_ulonglong2(pack2(y0, y0), pack2(y1, y1));
            syB[j] = make_ulonglong2(pack2(y2, y2), pack2(yn, yn));
        }
        __syncthreads();

        for (int jg = 0; jg < TILE; jg += GRP) {
            float gmin0 = 3.4e38f, gmin1 = 3.4e38f;
#pragma unroll
            for (int g = 0; g < GRP; g++) {
                u64 d2 = dist2(xa2, xb2, xc2, xx2, syA[jg + g], syB[jg + g]);
                float d0, d1;
                unpack2(d0, d1, d2);
                gmin0 = fminf(gmin0, d0);
                gmin1 = fminf(gmin1, d1);
            }
            // Rare: group improved the running min -> resolve index exactly.
            if (gmin0 < best0) {
                best0 = gmin0;
                for (int g = 0; g < GRP; g++) {
                    u64 d2 = dist2(xa2, xb2, xc2, xx2, syA[jg + g], syB[jg + g]);
                    float d0, d1; unpack2(d0, d1, d2);
                    if (d0 == best0) { idx0 = t0 + jg + g; break; }
                }
            }
            if (gmin1 < best1) {
                best1 = gmin1;
                for (int g = 0; g < GRP; g++) {
                    u64 d2 = dist2(xa2, xb2, xc2, xx2, syA[jg + g], syB[jg + g]);
                    float d0, d1; unpack2(d0, d1, d2);
                    if (d1 == best1) { idx1 = t0 + jg + g; break; }
                }
            }
        }
    }

    O[(long)b * NPTS + i0] = (float)idx0;
    O[(long)b * NPTS + i1] = (float)idx1;
}

extern "C" void kernel_launch(void* const* d_in, const int* in_sizes, int n_in,
                              void* d_out, int out_size) {
    const float* x1 = (const float*)d_in[0];
    const float* x2 = (const float*)d_in[1];
    float* out = (float*)d_out;

    dim3 grid(NPTS / XPB, BATCH, 2);   // 64 x-chunks, 8 batches, 2 directions
    nn_kernel<<<grid, THREADS>>>(x1, x2, out);
}

// round 13
// speedup vs baseline: 1.9367x; 1.2193x over previous
#include <cuda_runtime.h>

// ChamferIndex: bidirectional NN argmin, indices as FLOAT values.
// xyz1, xyz2: [8, 16384, 3] fp32. out (float32): [idx1(131072), idx2(131072)].
//
// Validated XLA value recipe (round 10): norms = mul + L2R add (no fma);
// dot = ascending fma chain; d = rn(xx + rn(yn - 2*dot)); first-min '<'.
//
// Perf: f32x2 packed over the J dimension (lanes = {j, j+1}), x operands
// duplicated once per thread (loop-invariant). Shared y stored as j-pairs ->
// 2 LDS.128 serve 2 x-points x 2 j's. Deferred argmin (group min + rare
// bit-exact rescan) keeps index ops off the hot path.

#define THREADS 128
#define XPT     2                    // x points per thread
#define XPB     (THREADS * XPT)      // 256 x points per block
#define TILEJ   2048                 // y points per smem tile
#define PAIRS   (TILEJ / 2)          // j-pairs per tile (32 KB smem)
#define GRP     8                    // j-pairs per deferred-argmin group (16 j)
#define BATCH   8
#define NPTS    16384
#define HALF    (BATCH * NPTS)

typedef unsigned long long u64;

__device__ __forceinline__ u64 pack2(float lo, float hi) {
    u64 r; asm("mov.b64 %0, {%1, %2};" : "=l"(r) : "f"(lo), "f"(hi)); return r;
}
__device__ __forceinline__ void unpack2(float& lo, float& hi, u64 v) {
    asm("mov.b64 {%0, %1}, %2;" : "=f"(lo), "=f"(hi) : "l"(v));
}
__device__ __forceinline__ u64 mul2(u64 a, u64 b) {
    u64 r; asm("mul.rn.f32x2 %0, %1, %2;" : "=l"(r) : "l"(a), "l"(b)); return r;
}
__device__ __forceinline__ u64 fma2(u64 a, u64 b, u64 c) {
    u64 r; asm("fma.rn.f32x2 %0, %1, %2, %3;" : "=l"(r) : "l"(a), "l"(b), "l"(c)); return r;
}
__device__ __forceinline__ u64 add2(u64 a, u64 b) {
    u64 r; asm("add.rn.f32x2 %0, %1, %2;" : "=l"(r) : "l"(a), "l"(b)); return r;
}
__device__ __forceinline__ u64 sub2(u64 a, u64 b) {
    u64 r; asm("sub.rn.f32x2 %0, %1, %2;" : "=l"(r) : "l"(a), "l"(b)); return r;
}

__device__ __forceinline__ float norm3_nofma(float a, float b, float c) {
    return __fadd_rn(__fadd_rn(__fmul_rn(a, a), __fmul_rn(b, b)),
                     __fmul_rn(c, c));
}

// Packed distance for one x-point (duplicated in xa2/xb2/xc2/xx2) against a
// j-pair (A,B). Lane-lo = j, lane-hi = j+1. Per-lane rn == scalar recipe.
__device__ __forceinline__ u64 dist2(u64 xa2, u64 xb2, u64 xc2, u64 xx2,
                                     ulonglong2 A, ulonglong2 B) {
    u64 dot = mul2(xa2, A.x);          // ascending fma chain
    dot = fma2(xb2, A.y, dot);
    dot = fma2(xc2, B.x, dot);
    u64 t = add2(dot, dot);            // 2*dot (exact)
    return add2(xx2, sub2(B.y, t));    // xx + (yn - 2*dot)
}

__global__ void nn_kernel(const float* __restrict__ x1,
                          const float* __restrict__ x2,
                          float* __restrict__ out)
{
    const int dir = blockIdx.z;
    const float* __restrict__ X = dir ? x2 : x1;
    const float* __restrict__ Y = dir ? x1 : x2;
    float* __restrict__ O = out + dir * HALF;

    const int b   = blockIdx.y;
    const int cx  = blockIdx.x;
    const int tid = threadIdx.x;

    // j-pair layout: syA[p] = {y0j,y0j' | y1j,y1j'}, syB[p] = {y2j,y2j' | ynj,ynj'}
    __shared__ ulonglong2 syA[PAIRS];
    __shared__ ulonglong2 syB[PAIRS];

    const int i0 = cx * XPB + tid;
    const int i1 = i0 + THREADS;
    const float* xp0 = X + ((long)b * NPTS + i0) * 3;
    const float* xp1 = X + ((long)b * NPTS + i1) * 3;
    float a0 = xp0[0], b0 = xp0[1], c0 = xp0[2];
    float a1 = xp1[0], b1 = xp1[1], c1 = xp1[2];

    // x operands duplicated across both f32x2 lanes (loop-invariant)
    const u64 xa20 = pack2(a0, a0), xb20 = pack2(b0, b0), xc20 = pack2(c0, c0);
    const u64 xa21 = pack2(a1, a1), xb21 = pack2(b1, b1), xc21 = pack2(c1, c1);
    float xn0 = norm3_nofma(a0, b0, c0), xn1 = norm3_nofma(a1, b1, c1);
    const u64 xx20 = pack2(xn0, xn0), xx21 = pack2(xn1, xn1);

    float best0 = 3.4e38f, best1 = 3.4e38f;
    int   idx0 = 0, idx1 = 0;

    const float* __restrict__ Yb = Y + (long)b * NPTS * 3;

    for (int t0 = 0; t0 < NPTS; t0 += TILEJ) {
        __syncthreads();
        for (int p = tid; p < PAIRS; p += THREADS) {
            const float* yp = Yb + (long)(t0 + 2 * p) * 3;   // 6 floats: j, j+1
            float u0 = yp[0], u1 = yp[1], u2 = yp[2];
            float v0 = yp[3], v1 = yp[4], v2 = yp[5];
            float un = norm3_nofma(u0, u1, u2);
            float vn = norm3_nofma(v0, v1, v2);
            syA[p] = make_ulonglong2(pack2(u0, v0), pack2(u1, v1));
            syB[p] = make_ulonglong2(pack2(u2, v2), pack2(un, vn));
        }
        __syncthreads();

        for (int pg = 0; pg < PAIRS; pg += GRP) {
            float gmin0 = 3.4e38f, gmin1 = 3.4e38f;
#pragma unroll
            for (int g = 0; g < GRP; g++) {
                ulonglong2 A = syA[pg + g];
                ulonglong2 B = syB[pg + g];
                u64 d20 = dist2(xa20, xb20, xc20, xx20, A, B);
                u64 d21 = dist2(xa21, xb21, xc21, xx21, A, B);
                float dl, dh;
                unpack2(dl, dh, d20);
                gmin0 = fminf(gmin0, dl); gmin0 = fminf(gmin0, dh);
                unpack2(dl, dh, d21);
                gmin1 = fminf(gmin1, dl); gmin1 = fminf(gmin1, dh);
            }
            // Rare: group improved running min -> resolve first index exactly
            // (identical instruction sequence -> bit-identical d values).
            if (gmin0 < best0) {
                best0 = gmin0;
                for (int g = 0; g < GRP; g++) {
                    u64 d2 = dist2(xa20, xb20, xc20, xx20, syA[pg + g], syB[pg + g]);
                    float dl, dh; unpack2(dl, dh, d2);
                    int jj = t0 + 2 * (pg + g);
                    if (dl == best0) { idx0 = jj; break; }
                    if (dh == best0) { idx0 = jj + 1; break; }
                }
            }
            if (gmin1 < best1) {
                best1 = gmin1;
                for (int g = 0; g < GRP; g++) {
                    u64 d2 = dist2(xa21, xb21, xc21, xx21, syA[pg + g], syB[pg + g]);
                    float dl, dh; unpack2(dl, dh, d2);
                    int jj = t0 + 2 * (pg + g);
                    if (dl == best1) { idx1 = jj; break; }
                    if (dh == best1) { idx1 = jj + 1; break; }
                }
            }
        }
    }

    O[(long)b * NPTS + i0] = (float)idx0;
    O[(long)b * NPTS + i1] = (float)idx1;
}

extern "C" void kernel_launch(void* const* d_in, const int* in_sizes, int n_in,
                              void* d_out, int out_size) {
    const float* x1 = (const float*)d_in[0];
    const float* x2 = (const float*)d_in[1];
    float* out = (float*)d_out;

    dim3 grid(NPTS / XPB, BATCH, 2);   // 64 x-chunks, 8 batches, 2 directions
    nn_kernel<<<grid, THREADS>>>(x1, x2, out);
}

// round 14
// speedup vs baseline: 2.2565x; 1.1651x over previous
#include <cuda_runtime.h>

// ChamferIndex: bidirectional NN argmin, indices as FLOAT values.
// xyz1, xyz2: [8, 16384, 3] fp32. out (float32): [idx1(131072), idx2(131072)].
//
// Validated XLA value recipe (round 10): norms = mul + L2R add (no fma);
// dot = ascending fma chain; d = rn(xx + rn(yn - 2*dot)); first-min '<'.
//
// Hot-loop strength reduction (bit-exact):
//  - smem holds 2*y components: fma chain yields 2*dot directly
//    (rounding commutes with exact x2 scaling) -> no add2(dot,dot).
//  - track u = rn(yn - 2dot) only; d = rn(xx+u) is monotone in u, so the
//    xx-add is deferred to once per 16-j group; strict '<' on group d keeps
//    exact first-min semantics (rescan recomputes full d bit-exactly).
//  - split lo/hi min accumulators to halve the FMNMX dependency chain.

#define THREADS 128
#define XPT     2                    // x points per thread
#define XPB     (THREADS * XPT)      // 256 x points per block
#define TILEJ   2048                 // y points per smem tile
#define PAIRS   (TILEJ / 2)          // j-pairs per tile (32 KB smem)
#define GRP     8                    // j-pairs per deferred-argmin group (16 j)
#define BATCH   8
#define NPTS    16384
#define HALF    (BATCH * NPTS)

typedef unsigned long long u64;

__device__ __forceinline__ u64 pack2(float lo, float hi) {
    u64 r; asm("mov.b64 %0, {%1, %2};" : "=l"(r) : "f"(lo), "f"(hi)); return r;
}
__device__ __forceinline__ void unpack2(float& lo, float& hi, u64 v) {
    asm("mov.b64 {%0, %1}, %2;" : "=f"(lo), "=f"(hi) : "l"(v));
}
__device__ __forceinline__ u64 mul2(u64 a, u64 b) {
    u64 r; asm("mul.rn.f32x2 %0, %1, %2;" : "=l"(r) : "l"(a), "l"(b)); return r;
}
__device__ __forceinline__ u64 fma2(u64 a, u64 b, u64 c) {
    u64 r; asm("fma.rn.f32x2 %0, %1, %2, %3;" : "=l"(r) : "l"(a), "l"(b), "l"(c)); return r;
}
__device__ __forceinline__ u64 sub2(u64 a, u64 b) {
    u64 r; asm("sub.rn.f32x2 %0, %1, %2;" : "=l"(r) : "l"(a), "l"(b)); return r;
}

__device__ __forceinline__ float norm3_nofma(float a, float b, float c) {
    return __fadd_rn(__fadd_rn(__fmul_rn(a, a), __fmul_rn(b, b)),
                     __fmul_rn(c, c));
}

// u = rn(yn - 2*dot) for a j-pair; A = {2y0|2y1}, B = {2y2|yn}.
// fma chain on doubled y gives exactly 2*dot (scaling by 2 is exact).
__device__ __forceinline__ u64 u_pair(u64 xa2, u64 xb2, u64 xc2,
                                      ulonglong2 A, ulonglong2 B) {
    u64 dot2 = mul2(xa2, A.x);         // 2*rn(xa*y0)
    dot2 = fma2(xb2, A.y, dot2);       // 2*rn(xb*y1 + .)
    dot2 = fma2(xc2, B.x, dot2);       // 2*rn(xc*y2 + .) == 2*dot exactly
    return sub2(B.y, dot2);            // rn(yn - 2*dot)
}

__global__ void nn_kernel(const float* __restrict__ x1,
                          const float* __restrict__ x2,
                          float* __restrict__ out)
{
    const int dir = blockIdx.z;
    const float* __restrict__ X = dir ? x2 : x1;
    const float* __restrict__ Y = dir ? x1 : x2;
    float* __restrict__ O = out + dir * HALF;

    const int b   = blockIdx.y;
    const int cx  = blockIdx.x;
    const int tid = threadIdx.x;

    __shared__ ulonglong2 syA[PAIRS];   // {2y0j,2y0j' | 2y1j,2y1j'}
    __shared__ ulonglong2 syB[PAIRS];   // {2y2j,2y2j' | ynj, ynj'}

    const int i0 = cx * XPB + tid;
    const int i1 = i0 + THREADS;
    const float* xp0 = X + ((long)b * NPTS + i0) * 3;
    const float* xp1 = X + ((long)b * NPTS + i1) * 3;
    float a0 = xp0[0], b0 = xp0[1], c0 = xp0[2];
    float a1 = xp1[0], b1 = xp1[1], c1 = xp1[2];

    const u64 xa20 = pack2(a0, a0), xb20 = pack2(b0, b0), xc20 = pack2(c0, c0);
    const u64 xa21 = pack2(a1, a1), xb21 = pack2(b1, b1), xc21 = pack2(c1, c1);
    const float xn0 = norm3_nofma(a0, b0, c0);
    const float xn1 = norm3_nofma(a1, b1, c1);

    float best0 = 3.4e38f, best1 = 3.4e38f;   // best exact d so far
    int   idx0 = 0, idx1 = 0;

    const float* __restrict__ Yb = Y + (long)b * NPTS * 3;

    for (int t0 = 0; t0 < NPTS; t0 += TILEJ) {
        __syncthreads();
        for (int p = tid; p < PAIRS; p += THREADS) {
            const float* yp = Yb + (long)(t0 + 2 * p) * 3;   // j, j+1
            float u0 = yp[0], u1 = yp[1], u2 = yp[2];
            float v0 = yp[3], v1 = yp[4], v2 = yp[5];
            float un = norm3_nofma(u0, u1, u2);
            float vn = norm3_nofma(v0, v1, v2);
            syA[p] = make_ulonglong2(pack2(2.0f * u0, 2.0f * v0),
                                     pack2(2.0f * u1, 2.0f * v1));
            syB[p] = make_ulonglong2(pack2(2.0f * u2, 2.0f * v2),
                                     pack2(un, vn));
        }
        __syncthreads();

        for (int pg = 0; pg < PAIRS; pg += GRP) {
            // split accumulators: lo-lane and hi-lane mins per x-point
            float gl0 = 3.4e38f, gh0 = 3.4e38f;
            float gl1 = 3.4e38f, gh1 = 3.4e38f;
#pragma unroll
            for (int g = 0; g < GRP; g++) {
                ulonglong2 A = syA[pg + g];
                ulonglong2 B = syB[pg + g];
                u64 up0 = u_pair(xa20, xb20, xc20, A, B);
                u64 up1 = u_pair(xa21, xb21, xc21, A, B);
                float ul, uh;
                unpack2(ul, uh, up0);
                gl0 = fminf(gl0, ul); gh0 = fminf(gh0, uh);
                unpack2(ul, uh, up1);
                gl1 = fminf(gl1, ul); gh1 = fminf(gh1, uh);
            }
            // group d = rn(xx + min u); strict '<' vs best keeps first-min.
            float gd0 = __fadd_rn(xn0, fminf(gl0, gh0));
            float gd1 = __fadd_rn(xn1, fminf(gl1, gh1));

            if (gd0 < best0) {
                best0 = gd0;
                for (int g = 0; g < GRP; g++) {
                    u64 up = u_pair(xa20, xb20, xc20, syA[pg + g], syB[pg + g]);
                    float ul, uh; unpack2(ul, uh, up);
                    int jj = t0 + 2 * (pg + g);
                    if (__fadd_rn(xn0, ul) == gd0) { idx0 = jj; break; }
                    if (__fadd_rn(xn0, uh) == gd0) { idx0 = jj + 1; break; }
                }
            }
            if (gd1 < best1) {
                best1 = gd1;
                for (int g = 0; g < GRP; g++) {
                    u64 up = u_pair(xa21, xb21, xc21, syA[pg + g], syB[pg + g]);
                    float ul, uh; unpack2(ul, uh, up);
                    int jj = t0 + 2 * (pg + g);
                    if (__fadd_rn(xn1, ul) == gd1) { idx1 = jj; break; }
                    if (__fadd_rn(xn1, uh) == gd1) { idx1 = jj + 1; break; }
                }
            }
        }
    }

    O[(long)b * NPTS + i0] = (float)idx0;
    O[(long)b * NPTS + i1] = (float)idx1;
}

extern "C" void kernel_launch(void* const* d_in, const int* in_sizes, int n_in,
                              void* d_out, int out_size) {
    const float* x1 = (const float*)d_in[0];
    const float* x2 = (const float*)d_in[1];
    float* out = (float*)d_out;

    dim3 grid(NPTS / XPB, BATCH, 2);   // 64 x-chunks, 8 batches, 2 directions
    nn_kernel<<<grid, THREADS>>>(x1, x2, out);
}

// round 16
// speedup vs baseline: 2.3342x; 1.0344x over previous
#include <cuda_runtime.h>

// ChamferIndex: bidirectional NN argmin, indices as FLOAT values.
// xyz1, xyz2: [8, 16384, 3] fp32. out (float32): [idx1(131072), idx2(131072)].
//
// Validated XLA value recipe (round 10): norms = mul + L2R add (no fma);
// dot = ascending fma chain; d = rn(xx + rn(yn - 2*dot)); first-min '<'.
//
// Perf structure (R14 + single-wave occupancy fix):
//  - f32x2 packed over J (lanes = {j, j+1}); x duplicated per thread.
//  - smem stores 2*y (exact doubling) -> fma chain yields 2*dot directly.
//  - track u = rn(yn - 2dot); xx-add deferred to group granularity
//    (d = rn(xx+u) monotone in u; strict '<' + bit-exact rescan = first-min).
//  - scalar FMNMX group-min accumulators (min.f32x2 doesn't exist on sm_100a).
//  - TILEJ=1024 -> 16.5 KB smem -> 8 CTAs/SM -> all 1024 blocks in ONE wave.

#define THREADS 128
#define XPT     2                    // x points per thread
#define XPB     (THREADS * XPT)      // 256 x points per block
#define TILEJ   1024                 // y points per smem tile
#define PAIRS   (TILEJ / 2)          // j-pairs per tile (16 KB smem)
#define GRP     8                    // j-pairs per deferred-argmin group (16 j)
#define BATCH   8
#define NPTS    16384
#define HALF    (BATCH * NPTS)

typedef unsigned long long u64;

__device__ __forceinline__ u64 pack2(float lo, float hi) {
    u64 r; asm("mov.b64 %0, {%1, %2};" : "=l"(r) : "f"(lo), "f"(hi)); return r;
}
__device__ __forceinline__ void unpack2(float& lo, float& hi, u64 v) {
    asm("mov.b64 {%0, %1}, %2;" : "=f"(lo), "=f"(hi) : "l"(v));
}
__device__ __forceinline__ u64 mul2(u64 a, u64 b) {
    u64 r; asm("mul.rn.f32x2 %0, %1, %2;" : "=l"(r) : "l"(a), "l"(b)); return r;
}
__device__ __forceinline__ u64 fma2(u64 a, u64 b, u64 c) {
    u64 r; asm("fma.rn.f32x2 %0, %1, %2, %3;" : "=l"(r) : "l"(a), "l"(b), "l"(c)); return r;
}
__device__ __forceinline__ u64 sub2(u64 a, u64 b) {
    u64 r; asm("sub.rn.f32x2 %0, %1, %2;" : "=l"(r) : "l"(a), "l"(b)); return r;
}

__device__ __forceinline__ float norm3_nofma(float a, float b, float c) {
    return __fadd_rn(__fadd_rn(__fmul_rn(a, a), __fmul_rn(b, b)),
                     __fmul_rn(c, c));
}

// u = rn(yn - 2*dot) for a j-pair; A = {2y0|2y1}, B = {2y2|yn}.
// fma chain on doubled y gives exactly 2*dot (x2 scaling is exact).
__device__ __forceinline__ u64 u_pair(u64 xa2, u64 xb2, u64 xc2,
                                      ulonglong2 A, ulonglong2 B) {
    u64 dot2 = mul2(xa2, A.x);
    dot2 = fma2(xb2, A.y, dot2);
    dot2 = fma2(xc2, B.x, dot2);       // == 2*dot exactly
    return sub2(B.y, dot2);            // rn(yn - 2*dot)
}

__global__ void nn_kernel(const float* __restrict__ x1,
                          const float* __restrict__ x2,
                          float* __restrict__ out)
{
    const int dir = blockIdx.z;
    const float* __restrict__ X = dir ? x2 : x1;
    const float* __restrict__ Y = dir ? x1 : x2;
    float* __restrict__ O = out + dir * HALF;

    const int b   = blockIdx.y;
    const int cx  = blockIdx.x;
    const int tid = threadIdx.x;

    __shared__ ulonglong2 syA[PAIRS];   // {2y0j,2y0j' | 2y1j,2y1j'}
    __shared__ ulonglong2 syB[PAIRS];   // {2y2j,2y2j' | ynj, ynj'}

    const int i0 = cx * XPB + tid;
    const int i1 = i0 + THREADS;
    const float* xp0 = X + ((long)b * NPTS + i0) * 3;
    const float* xp1 = X + ((long)b * NPTS + i1) * 3;
    float a0 = xp0[0], b0 = xp0[1], c0 = xp0[2];
    float a1 = xp1[0], b1 = xp1[1], c1 = xp1[2];

    const u64 xa20 = pack2(a0, a0), xb20 = pack2(b0, b0), xc20 = pack2(c0, c0);
    const u64 xa21 = pack2(a1, a1), xb21 = pack2(b1, b1), xc21 = pack2(c1, c1);
    const float xn0 = norm3_nofma(a0, b0, c0);
    const float xn1 = norm3_nofma(a1, b1, c1);

    float best0 = 3.4e38f, best1 = 3.4e38f;
    int   idx0 = 0, idx1 = 0;

    const float* __restrict__ Yb = Y + (long)b * NPTS * 3;

    for (int t0 = 0; t0 < NPTS; t0 += TILEJ) {
        __syncthreads();
        for (int p = tid; p < PAIRS; p += THREADS) {
            const float* yp = Yb + (long)(t0 + 2 * p) * 3;
            float u0 = yp[0], u1 = yp[1], u2 = yp[2];
            float v0 = yp[3], v1 = yp[4], v2 = yp[5];
            float un = norm3_nofma(u0, u1, u2);
            float vn = norm3_nofma(v0, v1, v2);
            syA[p] = make_ulonglong2(pack2(2.0f * u0, 2.0f * v0),
                                     pack2(2.0f * u1, 2.0f * v1));
            syB[p] = make_ulonglong2(pack2(2.0f * u2, 2.0f * v2),
                                     pack2(un, vn));
        }
        __syncthreads();

        for (int pg = 0; pg < PAIRS; pg += GRP) {
            float gl0 = 3.4e38f, gh0 = 3.4e38f;
            float gl1 = 3.4e38f, gh1 = 3.4e38f;
#pragma unroll
            for (int g = 0; g < GRP; g++) {
                ulonglong2 A = syA[pg + g];
                ulonglong2 B = syB[pg + g];
                u64 up0 = u_pair(xa20, xb20, xc20, A, B);
                u64 up1 = u_pair(xa21, xb21, xc21, A, B);
                float ul, uh;
                unpack2(ul, uh, up0);
                gl0 = fminf(gl0, ul); gh0 = fminf(gh0, uh);
                unpack2(ul, uh, up1);
                gl1 = fminf(gl1, ul); gh1 = fminf(gh1, uh);
            }
            float gd0 = __fadd_rn(xn0, fminf(gl0, gh0));
            float gd1 = __fadd_rn(xn1, fminf(gl1, gh1));

            if (gd0 < best0) {           // rare: resolve first index exactly
                best0 = gd0;
                for (int g = 0; g < GRP; g++) {
                    u64 up = u_pair(xa20, xb20, xc20, syA[pg + g], syB[pg + g]);
                    float ul, uh; unpack2(ul, uh, up);
                    int jj = t0 + 2 * (pg + g);
                    if (__fadd_rn(xn0, ul) == gd0) { idx0 = jj; break; }
                    if (__fadd_rn(xn0, uh) == gd0) { idx0 = jj + 1; break; }
                }
            }
            if (gd1 < best1) {
                best1 = gd1;
                for (int g = 0; g < GRP; g++) {
                    u64 up = u_pair(xa21, xb21, xc21, syA[pg + g], syB[pg + g]);
                    float ul, uh; unpack2(ul, uh, up);
                    int jj = t0 + 2 * (pg + g);
                    if (__fadd_rn(xn1, ul) == gd1) { idx1 = jj; break; }
                    if (__fadd_rn(xn1, uh) == gd1) { idx1 = jj + 1; break; }
                }
            }
        }
    }

    O[(long)b * NPTS + i0] = (float)idx0;
    O[(long)b * NPTS + i1] = (float)idx1;
}

extern "C" void kernel_launch(void* const* d_in, const int* in_sizes, int n_in,
                              void* d_out, int out_size) {
    const float* x1 = (const float*)d_in[0];
    const float* x2 = (const float*)d_in[1];
    float* out = (float*)d_out;

    dim3 grid(NPTS / XPB, BATCH, 2);   // 64 x-chunks, 8 batches, 2 directions
    nn_kernel<<<grid, THREADS>>>(x1, x2, out);
}